// round 14
// baseline (speedup 1.0000x reference)
#include <cuda_runtime.h>
#include <cuda_bf16.h>
#include <cstdint>

#define NBH   32
#define SSZ   2048
#define EE    256
#define HH    8
#define KKEY  2016
#define WWIN  33
#define TQ    96
#define NKT   21
#define NQT   22
#define NTILES (NQT * NBH)
#define NTH   512
#define NCHUNK 254
#define SCALE 0.17677669529663687f

#define QLD   104     // bf16 stride for QA/KB/P/V tiles (208 bytes)
#define GLD   131     // fp32 word stride for G (odd -> conflict-free diag reads)

// attn smem byte offsets
#define OFF_TQQ  0
#define OFF_TKK  768
#define OFF_TLEN 1536        // ends 2298
#define OFF_NEXT 2300        // next-tile broadcast slot
#define OFF_DEN  2304        // 96 floats -> ends 2688
#define OFF_QA   2688        // 128 x 208
#define OFF_KB0  29312       // 128 x 208
#define OFF_KB1  55936
#define OFF_G    82560       // 128 x 131 x 4 = 67072
#define OFF_PH   149632      // 96 x 208
#define OFF_PL   169600
#define OFF_VH0  189568      // 40 x 208
#define OFF_VL0  197888
#define OFF_VH1  206208
#define OFF_VL1  214528
#define SMEM_TOTAL 222848

// proj GEMM config: 128m x 64n tiles, K chunks of 64, double buffered
#define PJ_K    768
#define PJ_NCH  12
#define PJ_LDA  144
#define PJ_A0   0
#define PJ_B0   18432
#define PJ_A1   27648
#define PJ_B1   46080
#define PJ_SMEM 55296

// device scratch (no runtime allocation allowed)
__device__ __align__(16) __nv_bfloat16 g_xs[(size_t)8192 * PJ_K];   // [hi|lo|hi]
__device__ __align__(16) __nv_bfloat16 g_wT[(size_t)768 * PJ_K];    // [hi|hi|lo]
__device__ __align__(16) __nv_bfloat16 g_qA[(size_t)NBH * SSZ * 96];
__device__ __align__(16) __nv_bfloat16 g_kB[(size_t)NBH * SSZ * 96];
__device__ __align__(16) float         g_v [(size_t)NBH * SSZ * 32];
__device__ __align__(16) __nv_bfloat16 g_vsH[(size_t)NBH * 32 * KKEY];
__device__ __align__(16) __nv_bfloat16 g_vsL[(size_t)NBH * 32 * KKEY];
__device__ int g_ctr;

// ---------------- PTX helpers ----------------
__device__ __forceinline__ uint32_t smem_u32(const void* p) {
    uint32_t a;
    asm("{ .reg .u64 t; cvta.to.shared.u64 t, %1; cvt.u32.u64 %0, t; }"
        : "=r"(a) : "l"(p));
    return a;
}
__device__ __forceinline__ void mma16816(float* c, uint32_t a0, uint32_t a1,
                                         uint32_t a2, uint32_t a3,
                                         uint32_t b0, uint32_t b1)
{
    asm volatile(
        "mma.sync.aligned.m16n8k16.row.col.f32.bf16.bf16.f32 "
        "{%0,%1,%2,%3}, {%4,%5,%6,%7}, {%8,%9}, {%0,%1,%2,%3};"
        : "+f"(c[0]), "+f"(c[1]), "+f"(c[2]), "+f"(c[3])
        : "r"(a0), "r"(a1), "r"(a2), "r"(a3), "r"(b0), "r"(b1));
}
__device__ __forceinline__ void ldsm_x4(uint32_t addr, uint32_t& r0, uint32_t& r1,
                                        uint32_t& r2, uint32_t& r3)
{
    asm volatile("ldmatrix.sync.aligned.m8n8.x4.shared.b16 {%0,%1,%2,%3}, [%4];"
                 : "=r"(r0), "=r"(r1), "=r"(r2), "=r"(r3) : "r"(addr));
}
__device__ __forceinline__ void ldsm_x2(uint32_t addr, uint32_t& r0, uint32_t& r1)
{
    asm volatile("ldmatrix.sync.aligned.m8n8.x2.shared.b16 {%0,%1}, [%2];"
                 : "=r"(r0), "=r"(r1) : "r"(addr));
}
#define CP_ASYNC16(dst, src) \
    asm volatile("cp.async.cg.shared.global [%0], [%1], 16;" :: "r"(dst), "l"(src))
#define CP_COMMIT() asm volatile("cp.async.commit_group;" ::: "memory")
#define CP_WAIT0()  asm volatile("cp.async.wait_group 0;" ::: "memory")
#define CP_WAIT1()  asm volatile("cp.async.wait_group 1;" ::: "memory")

// ---------------------------------------------------------------------------
// Kernel 0a: split x -> packed bf16 [hi|lo|hi] rows of 768 (vectorized)
// ---------------------------------------------------------------------------
__global__ void xsplit_kernel(const float* __restrict__ x)
{
    int idx = blockIdx.x * blockDim.x + threadIdx.x;
    if (idx >= 8192 * 64) return;
    int m = idx >> 6, kq = (idx & 63) * 4;
    float4 v = *(const float4*)&x[(size_t)m * 256 + kq];
    float vv[4] = {v.x, v.y, v.z, v.w};
    __nv_bfloat16 h[4], l[4];
#pragma unroll
    for (int i = 0; i < 4; i++) {
        h[i] = __float2bfloat16(vv[i]);
        l[i] = __float2bfloat16(vv[i] - __bfloat162float(h[i]));
    }
    size_t rb = (size_t)m * PJ_K;
    *(uint2*)&g_xs[rb + kq]       = *(uint2*)h;
    *(uint2*)&g_xs[rb + 256 + kq] = *(uint2*)l;
    *(uint2*)&g_xs[rb + 512 + kq] = *(uint2*)h;
}

// ---------------------------------------------------------------------------
// Kernel 0b: split W^T -> packed bf16 [hi|hi|lo] (coalesced reads)
// ---------------------------------------------------------------------------
__global__ void wsplit_kernel(const float* __restrict__ Wq,
                              const float* __restrict__ Wk,
                              const float* __restrict__ Wv)
{
    int idx = blockIdx.x * blockDim.x + threadIdx.x;
    if (idx >= 768 * 256) return;
    int n = idx % 768, k = idx / 768;
    const float* Wsel = (n < 256) ? Wq : (n < 512) ? Wk : Wv;
    float v = Wsel[(size_t)k * 256 + (n & 255)];
    __nv_bfloat16 hi = __float2bfloat16(v);
    __nv_bfloat16 lo = __float2bfloat16(v - __bfloat162float(hi));
    size_t rb = (size_t)n * PJ_K;
    g_wT[rb + k] = hi;
    g_wT[rb + 256 + k] = hi;
    g_wT[rb + 512 + k] = lo;
}

// ---------------------------------------------------------------------------
// Kernel 1: HMMA projection, 128m x 64n tiles (grid 768, 3 CTAs/SM)
// ---------------------------------------------------------------------------
__device__ __forceinline__ void pj_load(uint32_t sb, uint32_t aoff, uint32_t boff,
                                        int m0, int n0, int ch, int tid)
{
    for (int i = tid; i < 1024; i += 256) {
        int r = i >> 3, cc = i & 7;
        const void* src = g_xs + (size_t)(m0 + r) * PJ_K + ch * 64 + cc * 8;
        CP_ASYNC16(sb + aoff + r * PJ_LDA + cc * 16, src);
    }
    for (int i = tid; i < 512; i += 256) {
        int r = i >> 3, cc = i & 7;
        const void* src = g_wT + (size_t)(n0 + r) * PJ_K + ch * 64 + cc * 8;
        CP_ASYNC16(sb + boff + r * PJ_LDA + cc * 16, src);
    }
}

__global__ __launch_bounds__(256, 3) void proj_mma_kernel(
    const float* __restrict__ bq, const float* __restrict__ bk,
    const float* __restrict__ bv)
{
    extern __shared__ char ps[];
    uint32_t sb = smem_u32(ps);
    int tid = threadIdx.x;
    int w = tid >> 5, lane = tid & 31;
    int g = lane >> 2, t = lane & 3;
    int m0 = blockIdx.y * 128, n0 = blockIdx.x * 64;
    int wm = w >> 1, wn = w & 1;

    float c[2][4][4];
#pragma unroll
    for (int i = 0; i < 2; i++)
#pragma unroll
        for (int j = 0; j < 4; j++)
#pragma unroll
            for (int k = 0; k < 4; k++) c[i][j][k] = 0.f;

    pj_load(sb, PJ_A0, PJ_B0, m0, n0, 0, tid);
    CP_COMMIT();

    for (int ch = 0; ch < PJ_NCH; ch++) {
        uint32_t ab = (ch & 1) ? PJ_A1 : PJ_A0;
        uint32_t bb = (ch & 1) ? PJ_B1 : PJ_B0;
        if (ch + 1 < PJ_NCH) {
            pj_load(sb, (ch & 1) ? PJ_A0 : PJ_A1, (ch & 1) ? PJ_B0 : PJ_B1,
                    m0, n0, ch + 1, tid);
            CP_COMMIT();
            CP_WAIT1();
        } else {
            CP_WAIT0();
        }
        __syncthreads();

        uint32_t aAddr = sb + ab + (uint32_t)(wm * 32 + (lane & 15)) * PJ_LDA
                       + (lane >> 4) * 16;
        uint32_t bAddr = sb + bb + (uint32_t)(wn * 32 + (lane & 15)) * PJ_LDA
                       + (lane >> 4) * 16;
#pragma unroll
        for (int k16 = 0; k16 < 4; k16++) {
            uint32_t b00, b01, b02, b03, b10, b11, b12, b13;
            ldsm_x4(bAddr + k16 * 32, b00, b01, b02, b03);
            ldsm_x4(bAddr + 16 * PJ_LDA + k16 * 32, b10, b11, b12, b13);
#pragma unroll
            for (int mt = 0; mt < 2; mt++) {
                uint32_t a0, a1, a2, a3;
                ldsm_x4(aAddr + (uint32_t)(mt * 16) * PJ_LDA + k16 * 32,
                        a0, a1, a2, a3);
                mma16816(c[mt][0], a0, a1, a2, a3, b00, b02);
                mma16816(c[mt][1], a0, a1, a2, a3, b01, b03);
                mma16816(c[mt][2], a0, a1, a2, a3, b10, b12);
                mma16816(c[mt][3], a0, a1, a2, a3, b11, b13);
            }
        }
        __syncthreads();
    }

    int msel = n0 >> 8;
    const float* bsel = (msel == 0) ? bq : (msel == 1) ? bk : bv;
#pragma unroll
    for (int mt = 0; mt < 2; mt++)
#pragma unroll
        for (int nt = 0; nt < 4; nt++)
#pragma unroll
            for (int j = 0; j < 4; j++) {
                int row = m0 + wm * 32 + mt * 16 + g + (j >> 1) * 8;
                int e = n0 + wn * 32 + nt * 8 + 2 * t + (j & 1);
                int ecol = e & 255;
                int h = ecol >> 5, d = ecol & 31;
                int b = row >> 11, s = row & 2047;
                float val = c[mt][nt][j] + bsel[ecol];
                if (msel == 2) {
                    g_v[(((size_t)(b * HH + h) * SSZ + s) * 32) + d] = val;
                } else {
                    __nv_bfloat16 hi = __float2bfloat16(val);
                    __nv_bfloat16 lo = __float2bfloat16(val - __bfloat162float(hi));
                    size_t rb = ((size_t)(b * HH + h) * SSZ + s) * 96;
                    if (msel == 0) {
                        g_qA[rb + d] = hi;
                        g_qA[rb + 32 + d] = lo;
                        g_qA[rb + 64 + d] = hi;
                    } else {
                        g_kB[rb + d] = hi;
                        g_kB[rb + 32 + d] = hi;
                        g_kB[rb + 64 + d] = lo;
                    }
                }
            }
}

// ---------------------------------------------------------------------------
// Kernel 2: sliding-window V sums, 8 outputs per thread (running sum)
// ---------------------------------------------------------------------------
__global__ void vsum_kernel()
{
    int idx = blockIdx.x * blockDim.x + threadIdx.x;
    const int KB8 = KKEY / 8;                  // 252
    const int total = NBH * 32 * KB8;
    if (idx >= total) return;
    int d  = idx & 31;
    int kb = (idx >> 5) % KB8;
    int bh = idx / (32 * KB8);
    int k0 = kb * 8;
    const float* vp = &g_v[((size_t)bh * SSZ + k0) * 32 + d];
    float s = 0.f;
#pragma unroll
    for (int w = 0; w < WWIN; w++) s += vp[w * 32];
    __nv_bfloat16 h8[8], l8[8];
#pragma unroll
    for (int i = 0; i < 8; i++) {
        __nv_bfloat16 hi = __float2bfloat16(s);
        h8[i] = hi;
        l8[i] = __float2bfloat16(s - __bfloat162float(hi));
        if (i < 7) s += vp[(WWIN + i) * 32] - vp[i * 32];
    }
    size_t o = ((size_t)bh * 32 + d) * KKEY + k0;
    *(uint4*)&g_vsH[o] = *(uint4*)h8;
    *(uint4*)&g_vsL[o] = *(uint4*)l8;
}

// ---------------------------------------------------------------------------
// work-queue counter init
// ---------------------------------------------------------------------------
__global__ void ctr_init_kernel() { g_ctr = 148; }

// ---------------------------------------------------------------------------
// G phase split: register-accumulate (stage1) + store (stage2)
// 8 warps as 4m x 2n of 32x64; cG[half][mi][ni][j]
// ---------------------------------------------------------------------------
__device__ __forceinline__ void compute_G_regs(uint32_t sb, uint32_t kbuf_off,
                                               int w, int lane,
                                               float cG[2][2][4][4])
{
    int mw = w >> 1, nw = w & 1;
    int r0 = mw * 32, kb = nw * 64;
    uint32_t aG0 = sb + OFF_QA + (uint32_t)(r0 + (lane & 15)) * 208
                 + (lane >> 4) * 16;
    uint32_t aG1 = aG0 + 16 * 208;
    uint32_t bRow4 = ((uint32_t)(lane >> 4) * 8 + (lane & 7)) * 208
                   + ((lane >> 3) & 1) * 16;
    uint32_t kbase = sb + kbuf_off;

#pragma unroll
    for (int half = 0; half < 2; half++) {
#pragma unroll
        for (int mi = 0; mi < 2; mi++)
#pragma unroll
            for (int ni = 0; ni < 4; ni++)
#pragma unroll
                for (int j = 0; j < 4; j++) cG[half][mi][ni][j] = 0.f;
#pragma unroll
        for (int ks = 0; ks < 6; ks++) {
            uint32_t a0, a1, a2, a3, a4, a5, a6, a7;
            ldsm_x4(aG0 + ks * 32, a0, a1, a2, a3);
            ldsm_x4(aG1 + ks * 32, a4, a5, a6, a7);
#pragma unroll
            for (int p2 = 0; p2 < 2; p2++) {
                int colb = kb + half * 32 + p2 * 16;
                uint32_t b0, b1, b2, b3;
                ldsm_x4(kbase + (uint32_t)colb * 208 + bRow4 + ks * 32,
                        b0, b1, b2, b3);
                mma16816(cG[half][0][2 * p2],     a0, a1, a2, a3, b0, b1);
                mma16816(cG[half][1][2 * p2],     a4, a5, a6, a7, b0, b1);
                mma16816(cG[half][0][2 * p2 + 1], a0, a1, a2, a3, b2, b3);
                mma16816(cG[half][1][2 * p2 + 1], a4, a5, a6, a7, b2, b3);
            }
        }
    }
}

__device__ __forceinline__ void sts_G(char* sm, int w, int lane,
                                      float cG[2][2][4][4])
{
    float* G = (float*)(sm + OFF_G);
    int g = lane >> 2, t = lane & 3;
    int mw = w >> 1, nw = w & 1;
    int r0 = mw * 32, kb = nw * 64;
#pragma unroll
    for (int half = 0; half < 2; half++)
#pragma unroll
        for (int mi = 0; mi < 2; mi++)
#pragma unroll
            for (int ni = 0; ni < 4; ni++) {
                int r = r0 + mi * 16 + g;
                int col = kb + half * 32 + ni * 8 + 2 * t;
                G[r * GLD + col]           = cG[half][mi][ni][0];
                G[r * GLD + col + 1]       = cG[half][mi][ni][1];
                G[(r + 8) * GLD + col]     = cG[half][mi][ni][2];
                G[(r + 8) * GLD + col + 1] = cG[half][mi][ni][3];
            }
}

// ---------------------------------------------------------------------------
// Kernel 3: persistent HMMA attention; stage1 = C(kt) || G(kt+1)-in-regs,
// stage2 = G STS || PV(kt). Prefetch by G-warps at stage1 entry.
// ---------------------------------------------------------------------------
__global__ __launch_bounds__(NTH, 1) void attn_kernel(float* __restrict__ out)
{
    extern __shared__ char sm[];
    uint32_t sb = smem_u32(sm);
    uint16_t* tqq  = (uint16_t*)(sm + OFF_TQQ);
    uint16_t* tkk  = (uint16_t*)(sm + OFF_TKK);
    uint16_t* tlen = (uint16_t*)(sm + OFF_TLEN);
    float* den_s = (float*)(sm + OFF_DEN);
    int* next_s = (int*)(sm + OFF_NEXT);
    float* G = (float*)(sm + OFF_G);
    __nv_bfloat16* PH = (__nv_bfloat16*)(sm + OFF_PH);
    __nv_bfloat16* PL = (__nv_bfloat16*)(sm + OFF_PL);

    int tid = threadIdx.x;
    int w = tid >> 5, lane = tid & 31;
    int g = lane >> 2, t = lane & 3;

    if (tid == 0) {
        // chunk table: chunks of len<=64, t0-major then diagonal (254 chunks)
        int c = 0;
        for (int t0 = 0; t0 < TQ; t0 += 64) {
            for (int d = -95; d <= 95; d++) {
                int ad = d < 0 ? -d : d;
                int L = 96 - ad;
                if (t0 >= L) continue;
                tqq[c] = (uint16_t)((d > 0 ? d : 0) + t0);
                tkk[c] = (uint16_t)((d > 0 ? 0 : -d) + t0);
                int l = L - t0; tlen[c] = (uint16_t)(l < 64 ? l : 64);
                c++;
            }
        }
    }
    // const V rows 32..39 for BOTH buffers; VH row32 = ones (denominator)
    for (int idx = tid; idx < 416; idx += NTH) {
        int buf = idx / 208, rem = idx % 208;
        int tt = rem / 104, r2 = rem % 104;
        int r = 32 + r2 / 13, cb = r2 % 13;
        uint4 v = make_uint4(0, 0, 0, 0);
        if (tt == 0 && r == 32)
            v = make_uint4(0x3F803F80u, 0x3F803F80u, 0x3F803F80u, 0x3F803F80u);
        int off = tt ? (buf ? OFF_VL1 : OFF_VL0) : (buf ? OFF_VH1 : OFF_VH0);
        *(uint4*)(sm + off + r * 208 + cb * 16) = v;
    }

    // PV addressing constants (warps 8-13 stripes; 14/15 den tiles)
    uint32_t bRow4 = ((uint32_t)(lane >> 4) * 8 + (lane & 7)) * 208
                   + ((lane >> 3) & 1) * 16;
    uint32_t bRow2 = (uint32_t)(lane & 7) * 208 + ((lane >> 3) & 1) * 16;
    uint32_t aPHf = sb + OFF_PH + (uint32_t)((w - 8) * 16 + (lane & 15)) * 208
                  + (lane >> 4) * 16;
    uint32_t aPLf = aPHf + (OFF_PL - OFF_PH);

    float acc[4][4];     // PV accumulators (warps 8-15)
    float cG[2][2][4][4];// G accumulators (warps 0-7)
    int tile = blockIdx.x;

    for (;;) {
        int qt = tile % NQT, bh = tile / NQT;
        int q0 = qt * TQ;
        const uint4* qsrc = (const uint4*)(g_qA + (size_t)bh * SSZ * 96);
        const uint4* ksrc = (const uint4*)(g_kB + (size_t)bh * SSZ * 96);

        // per-tile prologue: Q halo, KB(0)->kb0, KB(1)->kb1, V(0)->v0
        for (int idx = tid; idx < 128 * 12; idx += NTH) {
            int r = idx / 12, cb = idx % 12;
            int gq = q0 - 16 + r;
            if (gq >= 0 && gq < SSZ)
                CP_ASYNC16(sb + OFF_QA + r * 208 + cb * 16,
                           (const void*)(qsrc + (size_t)gq * 12 + cb));
            else
                *(uint4*)(sm + OFF_QA + r * 208 + cb * 16) = make_uint4(0, 0, 0, 0);
        }
        for (int idx = tid; idx < 1536; idx += NTH) {
            int r = idx / 12, cb = idx % 12;
            CP_ASYNC16(sb + OFF_KB0 + r * 208 + cb * 16,
                       (const void*)(ksrc + (size_t)r * 12 + cb));
            CP_ASYNC16(sb + OFF_KB1 + r * 208 + cb * 16,
                       (const void*)(ksrc + (size_t)(TQ + r) * 12 + cb));
        }
        for (int idx = tid; idx < 768; idx += NTH) {
            int tt = idx / 384, rem = idx % 384;
            int d = rem / 12, cb = rem % 12;
            const __nv_bfloat16* src = (tt ? g_vsL : g_vsH)
                + ((size_t)bh * 32 + d) * KKEY + cb * 8;
            CP_ASYNC16(sb + (tt ? OFF_VL0 : OFF_VH0) + d * 208 + cb * 16,
                       (const void*)src);
        }
        CP_COMMIT();
        CP_WAIT0();
        __syncthreads();

        // G(0): regs then immediate store (same warps, no barrier needed)
        if (w < 8) {
            compute_G_regs(sb, OFF_KB0, w, lane, cG);
            sts_G(sm, w, lane, cG);
        }

#pragma unroll
        for (int i = 0; i < 4; i++)
#pragma unroll
            for (int j = 0; j < 4; j++) acc[i][j] = 0.f;

        for (int kt = 0; kt < NKT; kt++) {
            __syncthreads();   // G(kt) visible; PV(kt-1) done; prefetches waited

            // ===== stage 1: C(kt) on warps 8-15 || prefetch+G(kt+1) on 0-7 ===
            if (w < 8) {
                // prefetch KB(kt+2) and V(kt+1) (256 threads)
                if (kt + 2 < NKT) {
                    int k0n = (kt + 2) * TQ;
                    uint32_t kdst = sb + ((kt & 1) ? OFF_KB1 : OFF_KB0);
                    for (int idx = tid; idx < 1536; idx += 256) {
                        int r = idx / 12, cb = idx % 12;
                        CP_ASYNC16(kdst + r * 208 + cb * 16,
                                   (const void*)(ksrc + (size_t)(k0n + r) * 12 + cb));
                    }
                }
                if (kt + 1 < NKT) {
                    int k0n = (kt + 1) * TQ;
                    for (int idx = tid; idx < 768; idx += 256) {
                        int tt = idx / 384, rem = idx % 384;
                        int d = rem / 12, cb = rem % 12;
                        const __nv_bfloat16* src = (tt ? g_vsL : g_vsH)
                            + ((size_t)bh * 32 + d) * KKEY + k0n + cb * 8;
                        int off = tt ? (((kt + 1) & 1) ? OFF_VL1 : OFF_VL0)
                                     : (((kt + 1) & 1) ? OFF_VH1 : OFF_VH0);
                        CP_ASYNC16(sb + off + d * 208 + cb * 16, (const void*)src);
                    }
                }
                CP_COMMIT();
                if (kt + 1 < NKT)
                    compute_G_regs(sb, ((kt + 1) & 1) ? OFF_KB1 : OFF_KB0,
                                   w, lane, cG);
            } else {
                CP_COMMIT();   // empty group keeps per-thread counts aligned
                int ci = tid - 256;
                if (ci < NCHUNK) {
                    int qq = tqq[ci], kk = tkk[ci], len = tlen[ci];
                    float s = 0.f;
#pragma unroll
                    for (int ww = 0; ww < WWIN; ww++)
                        s += G[(qq + ww) * GLD + kk + ww];
                    {
                        float p = __expf(s * SCALE);
                        __nv_bfloat16 hi = __float2bfloat16(p);
                        __nv_bfloat16 lo = __float2bfloat16(p - __bfloat162float(hi));
                        int off = qq * QLD + kk;
                        PH[off] = hi;
                        PL[off] = lo;
                    }
#pragma unroll 4
                    for (int u = 1; u < 32; u++) {
                        int uu = (u < len) ? u : (len - 1);
                        s += G[(qq + uu + 32) * GLD + (kk + uu + 32)]
                           - G[(qq + uu - 1) * GLD + (kk + uu - 1)];
                        if (u < len) {
                            float p = __expf(s * SCALE);
                            __nv_bfloat16 hi = __float2bfloat16(p);
                            __nv_bfloat16 lo = __float2bfloat16(p - __bfloat162float(hi));
                            int off = (qq + u) * QLD + (kk + u);
                            PH[off] = hi;
                            PL[off] = lo;
                        }
                    }
                    if (len > 32) {
#pragma unroll 4
                        for (int u = 32; u < 64; u++) {
                            int uu = (u < len) ? u : (len - 1);
                            s += G[(qq + uu + 32) * GLD + (kk + uu + 32)]
                               - G[(qq + uu - 1) * GLD + (kk + uu - 1)];
                            if (u < len) {
                                float p = __expf(s * SCALE);
                                __nv_bfloat16 hi = __float2bfloat16(p);
                                __nv_bfloat16 lo = __float2bfloat16(p - __bfloat162float(hi));
                                int off = (qq + u) * QLD + (kk + u);
                                PH[off] = hi;
                                PL[off] = lo;
                            }
                        }
                    }
                }
            }
            __syncthreads();   // P(kt) visible; C done reading G(kt)

            // ===== stage 2: G STS on warps 0-7 || PV(kt) on warps 8-15 =====
            if (w < 8) {
                if (kt + 1 < NKT) sts_G(sm, w, lane, cG);
            } else {
                uint32_t vhb = sb + ((kt & 1) ? OFF_VH1 : OFF_VH0);
                uint32_t vlb = sb + ((kt & 1) ? OFF_VL1 : OFF_VL0);
                if (w < 14) {
#pragma unroll
                    for (int pass = 0; pass < 3; pass++) {
                        uint32_t Ab = (pass == 1) ? aPLf : aPHf;
                        uint32_t Bb = (pass == 2) ? vlb : vhb;
#pragma unroll
                        for (int ks = 0; ks < 6; ks++) {
                            uint32_t a0, a1, a2, a3;
                            ldsm_x4(Ab + ks * 32, a0, a1, a2, a3);
                            uint32_t b0, b1, b2, b3;
                            ldsm_x4(Bb + bRow4 + ks * 32, b0, b1, b2, b3);
                            mma16816(acc[0], a0, a1, a2, a3, b0, b1);
                            mma16816(acc[1], a0, a1, a2, a3, b2, b3);
                            ldsm_x4(Bb + 16 * 208 + bRow4 + ks * 32, b0, b1, b2, b3);
                            mma16816(acc[2], a0, a1, a2, a3, b0, b1);
                            mma16816(acc[3], a0, a1, a2, a3, b2, b3);
                        }
                    }
                } else {
                    int base = (w - 14) * 3;
#pragma unroll
                    for (int st = 0; st < 3; st++) {
                        uint32_t aPh = sb + OFF_PH
                            + (uint32_t)((base + st) * 16 + (lane & 15)) * 208
                            + (lane >> 4) * 16;
                        uint32_t aPl = aPh + (OFF_PL - OFF_PH);
#pragma unroll
                        for (int pass = 0; pass < 3; pass++) {
                            uint32_t Ab = (pass == 1) ? aPl : aPh;
                            uint32_t Bb = (pass == 2) ? vlb : vhb;
#pragma unroll
                            for (int ks = 0; ks < 6; ks++) {
                                uint32_t a0, a1, a2, a3;
                                ldsm_x4(Ab + ks * 32, a0, a1, a2, a3);
                                uint32_t b0, b1;
                                ldsm_x2(Bb + 32 * 208 + bRow2 + ks * 32, b0, b1);
                                mma16816(acc[st], a0, a1, a2, a3, b0, b1);
                            }
                        }
                    }
                }
            }
            CP_WAIT0();   // own prefetches landed before next-iter barrier
        }

        // denominator from warps 14/15 (col 32 -> t==0, j 0/2)
        if (w >= 14 && t == 0) {
            int base = (w - 14) * 3;
#pragma unroll
            for (int st = 0; st < 3; st++) {
                den_s[(base + st) * 16 + g]     = acc[st][0];
                den_s[(base + st) * 16 + g + 8] = acc[st][2];
            }
        }
        __syncthreads();

        if (w >= 8 && w < 14) {
            int stripe = w - 8;
            int b = bh >> 3, h = bh & 7;
#pragma unroll
            for (int mi = 0; mi < 2; mi++) {
                int rr = stripe * 16 + g + mi * 8;
                int q = q0 + rr;
                if (q < SSZ) {
                    float dinv = 1.f / den_s[rr];
                    float* orow = out + ((size_t)b * SSZ + q) * EE + h * 32;
#pragma unroll
                    for (int nt = 0; nt < 4; nt++) {
                        int col = nt * 8 + 2 * t;
                        orow[col]     = acc[nt][mi * 2]     * dinv;
                        orow[col + 1] = acc[nt][mi * 2 + 1] * dinv;
                    }
                }
            }
        }
        if (tid == 0) next_s[0] = atomicAdd(&g_ctr, 1);
        __syncthreads();   // next tile visible; everyone done with QA/P/V/den
        tile = next_s[0];
        if (tile >= NTILES) break;
    }
}

// ---------------------------------------------------------------------------
extern "C" void kernel_launch(void* const* d_in, const int* in_sizes, int n_in,
                              void* d_out, int out_size)
{
    const float* x  = (const float*)d_in[0];
    const float* Wq = (const float*)d_in[1];
    const float* bq = (const float*)d_in[2];
    const float* Wk = (const float*)d_in[3];
    const float* bk = (const float*)d_in[4];
    const float* Wv = (const float*)d_in[5];
    const float* bv = (const float*)d_in[6];
    float* out = (float*)d_out;

    xsplit_kernel<<<(8192 * 64 + 255) / 256, 256>>>(x);
    wsplit_kernel<<<(768 * 256 + 255) / 256, 256>>>(Wq, Wk, Wv);
    ctr_init_kernel<<<1, 1>>>();
    {
        cudaFuncSetAttribute(proj_mma_kernel,
                             cudaFuncAttributeMaxDynamicSharedMemorySize,
                             PJ_SMEM);
        dim3 grid(12, 64);
        proj_mma_kernel<<<grid, 256, PJ_SMEM>>>(bq, bk, bv);
    }
    {
        const int total = NBH * 32 * (KKEY / 8);
        vsum_kernel<<<(total + 255) / 256, 256>>>();
    }
    {
        cudaFuncSetAttribute(attn_kernel,
                             cudaFuncAttributeMaxDynamicSharedMemorySize,
                             SMEM_TOTAL);
        attn_kernel<<<148, NTH, SMEM_TOTAL>>>(out);
    }
}

// round 17
// speedup vs baseline: 1.3447x; 1.3447x over previous
#include <cuda_runtime.h>
#include <cuda_bf16.h>
#include <cstdint>

#define NBH   32
#define SSZ   2048
#define EE    256
#define HH    8
#define KKEY  2016
#define WWIN  33
#define TQ    96
#define NKT   21
#define NQT   22
#define NTILES (NQT * NBH)
#define NTH   512
#define NCHUNK 381
#define SCALE 0.17677669529663687f

#define QLD   104     // bf16 stride for QA/KB/P/V tiles (208 bytes)
#define GLD   131     // fp32 word stride for G (odd -> conflict-free diag reads)

// attn smem byte offsets
#define OFF_TQQ  0
#define OFF_TKK  768
#define OFF_TLEN 1536        // ends 2298
#define OFF_NEXT 2300        // next-tile broadcast slot (4B, in the gap)
#define OFF_DEN  2304        // 96 floats -> ends 2688
#define OFF_QA   2688        // 128 x 208
#define OFF_KB0  29312       // 128 x 208
#define OFF_KB1  55936
#define OFF_G    82560       // 128 x 131 x 4 = 67072
#define OFF_PH   149632      // 96 x 208
#define OFF_PL   169600
#define OFF_VH0  189568      // 40 x 208
#define OFF_VL0  197888
#define OFF_VH1  206208
#define OFF_VL1  214528
#define SMEM_TOTAL 222848

// proj GEMM config: 128m x 64n tiles, K chunks of 64, double buffered
#define PJ_K    768
#define PJ_NCH  12
#define PJ_LDA  144
#define PJ_A0   0
#define PJ_B0   18432
#define PJ_A1   27648
#define PJ_B1   46080
#define PJ_SMEM 55296

// device scratch (no runtime allocation allowed)
__device__ __align__(16) __nv_bfloat16 g_xs[(size_t)8192 * PJ_K];   // [hi|lo|hi]
__device__ __align__(16) __nv_bfloat16 g_wT[(size_t)768 * PJ_K];    // [hi|hi|lo]
__device__ __align__(16) __nv_bfloat16 g_qA[(size_t)NBH * SSZ * 96];
__device__ __align__(16) __nv_bfloat16 g_kB[(size_t)NBH * SSZ * 96];
__device__ __align__(16) float         g_v [(size_t)NBH * SSZ * 32];
__device__ __align__(16) __nv_bfloat16 g_vsH[(size_t)NBH * 32 * KKEY];
__device__ __align__(16) __nv_bfloat16 g_vsL[(size_t)NBH * 32 * KKEY];
__device__ int g_ctr;

// ---------------- PTX helpers ----------------
__device__ __forceinline__ uint32_t smem_u32(const void* p) {
    uint32_t a;
    asm("{ .reg .u64 t; cvta.to.shared.u64 t, %1; cvt.u32.u64 %0, t; }"
        : "=r"(a) : "l"(p));
    return a;
}
__device__ __forceinline__ void mma16816(float* c, uint32_t a0, uint32_t a1,
                                         uint32_t a2, uint32_t a3,
                                         uint32_t b0, uint32_t b1)
{
    asm volatile(
        "mma.sync.aligned.m16n8k16.row.col.f32.bf16.bf16.f32 "
        "{%0,%1,%2,%3}, {%4,%5,%6,%7}, {%8,%9}, {%0,%1,%2,%3};"
        : "+f"(c[0]), "+f"(c[1]), "+f"(c[2]), "+f"(c[3])
        : "r"(a0), "r"(a1), "r"(a2), "r"(a3), "r"(b0), "r"(b1));
}
__device__ __forceinline__ void ldsm_x4(uint32_t addr, uint32_t& r0, uint32_t& r1,
                                        uint32_t& r2, uint32_t& r3)
{
    asm volatile("ldmatrix.sync.aligned.m8n8.x4.shared.b16 {%0,%1,%2,%3}, [%4];"
                 : "=r"(r0), "=r"(r1), "=r"(r2), "=r"(r3) : "r"(addr));
}
__device__ __forceinline__ void ldsm_x2(uint32_t addr, uint32_t& r0, uint32_t& r1)
{
    asm volatile("ldmatrix.sync.aligned.m8n8.x2.shared.b16 {%0,%1}, [%2];"
                 : "=r"(r0), "=r"(r1) : "r"(addr));
}
#define CP_ASYNC16(dst, src) \
    asm volatile("cp.async.cg.shared.global [%0], [%1], 16;" :: "r"(dst), "l"(src))
#define CP_COMMIT() asm volatile("cp.async.commit_group;" ::: "memory")
#define CP_WAIT0()  asm volatile("cp.async.wait_group 0;" ::: "memory")
#define CP_WAIT1()  asm volatile("cp.async.wait_group 1;" ::: "memory")

// ---------------------------------------------------------------------------
// Kernel 0a: split x -> packed bf16 [hi|lo|hi] rows of 768 (vectorized)
// ---------------------------------------------------------------------------
__global__ void xsplit_kernel(const float* __restrict__ x)
{
    int idx = blockIdx.x * blockDim.x + threadIdx.x;
    if (idx >= 8192 * 64) return;
    int m = idx >> 6, kq = (idx & 63) * 4;
    float4 v = *(const float4*)&x[(size_t)m * 256 + kq];
    float vv[4] = {v.x, v.y, v.z, v.w};
    __nv_bfloat16 h[4], l[4];
#pragma unroll
    for (int i = 0; i < 4; i++) {
        h[i] = __float2bfloat16(vv[i]);
        l[i] = __float2bfloat16(vv[i] - __bfloat162float(h[i]));
    }
    size_t rb = (size_t)m * PJ_K;
    *(uint2*)&g_xs[rb + kq]       = *(uint2*)h;
    *(uint2*)&g_xs[rb + 256 + kq] = *(uint2*)l;
    *(uint2*)&g_xs[rb + 512 + kq] = *(uint2*)h;
}

// ---------------------------------------------------------------------------
// Kernel 0b: split W^T -> packed bf16 [hi|hi|lo] (coalesced reads)
// ---------------------------------------------------------------------------
__global__ void wsplit_kernel(const float* __restrict__ Wq,
                              const float* __restrict__ Wk,
                              const float* __restrict__ Wv)
{
    int idx = blockIdx.x * blockDim.x + threadIdx.x;
    if (idx >= 768 * 256) return;
    int n = idx % 768, k = idx / 768;
    const float* Wsel = (n < 256) ? Wq : (n < 512) ? Wk : Wv;
    float v = Wsel[(size_t)k * 256 + (n & 255)];
    __nv_bfloat16 hi = __float2bfloat16(v);
    __nv_bfloat16 lo = __float2bfloat16(v - __bfloat162float(hi));
    size_t rb = (size_t)n * PJ_K;
    g_wT[rb + k] = hi;
    g_wT[rb + 256 + k] = hi;
    g_wT[rb + 512 + k] = lo;
}

// ---------------------------------------------------------------------------
// Kernel 1: HMMA projection, 128m x 64n tiles (grid 768, 3 CTAs/SM)
// ---------------------------------------------------------------------------
__device__ __forceinline__ void pj_load(uint32_t sb, uint32_t aoff, uint32_t boff,
                                        int m0, int n0, int ch, int tid)
{
    for (int i = tid; i < 1024; i += 256) {
        int r = i >> 3, cc = i & 7;
        const void* src = g_xs + (size_t)(m0 + r) * PJ_K + ch * 64 + cc * 8;
        CP_ASYNC16(sb + aoff + r * PJ_LDA + cc * 16, src);
    }
    for (int i = tid; i < 512; i += 256) {
        int r = i >> 3, cc = i & 7;
        const void* src = g_wT + (size_t)(n0 + r) * PJ_K + ch * 64 + cc * 8;
        CP_ASYNC16(sb + boff + r * PJ_LDA + cc * 16, src);
    }
}

__global__ __launch_bounds__(256, 3) void proj_mma_kernel(
    const float* __restrict__ bq, const float* __restrict__ bk,
    const float* __restrict__ bv)
{
    extern __shared__ char ps[];
    uint32_t sb = smem_u32(ps);
    int tid = threadIdx.x;
    int w = tid >> 5, lane = tid & 31;
    int g = lane >> 2, t = lane & 3;
    int m0 = blockIdx.y * 128, n0 = blockIdx.x * 64;
    int wm = w >> 1, wn = w & 1;

    float c[2][4][4];
#pragma unroll
    for (int i = 0; i < 2; i++)
#pragma unroll
        for (int j = 0; j < 4; j++)
#pragma unroll
            for (int k = 0; k < 4; k++) c[i][j][k] = 0.f;

    pj_load(sb, PJ_A0, PJ_B0, m0, n0, 0, tid);
    CP_COMMIT();

    for (int ch = 0; ch < PJ_NCH; ch++) {
        uint32_t ab = (ch & 1) ? PJ_A1 : PJ_A0;
        uint32_t bb = (ch & 1) ? PJ_B1 : PJ_B0;
        if (ch + 1 < PJ_NCH) {
            pj_load(sb, (ch & 1) ? PJ_A0 : PJ_A1, (ch & 1) ? PJ_B0 : PJ_B1,
                    m0, n0, ch + 1, tid);
            CP_COMMIT();
            CP_WAIT1();
        } else {
            CP_WAIT0();
        }
        __syncthreads();

        uint32_t aAddr = sb + ab + (uint32_t)(wm * 32 + (lane & 15)) * PJ_LDA
                       + (lane >> 4) * 16;
        uint32_t bAddr = sb + bb + (uint32_t)(wn * 32 + (lane & 15)) * PJ_LDA
                       + (lane >> 4) * 16;
#pragma unroll
        for (int k16 = 0; k16 < 4; k16++) {
            uint32_t b00, b01, b02, b03, b10, b11, b12, b13;
            ldsm_x4(bAddr + k16 * 32, b00, b01, b02, b03);
            ldsm_x4(bAddr + 16 * PJ_LDA + k16 * 32, b10, b11, b12, b13);
#pragma unroll
            for (int mt = 0; mt < 2; mt++) {
                uint32_t a0, a1, a2, a3;
                ldsm_x4(aAddr + (uint32_t)(mt * 16) * PJ_LDA + k16 * 32,
                        a0, a1, a2, a3);
                mma16816(c[mt][0], a0, a1, a2, a3, b00, b02);
                mma16816(c[mt][1], a0, a1, a2, a3, b01, b03);
                mma16816(c[mt][2], a0, a1, a2, a3, b10, b12);
                mma16816(c[mt][3], a0, a1, a2, a3, b11, b13);
            }
        }
        __syncthreads();
    }

    int msel = n0 >> 8;
    const float* bsel = (msel == 0) ? bq : (msel == 1) ? bk : bv;
#pragma unroll
    for (int mt = 0; mt < 2; mt++)
#pragma unroll
        for (int nt = 0; nt < 4; nt++)
#pragma unroll
            for (int j = 0; j < 4; j++) {
                int row = m0 + wm * 32 + mt * 16 + g + (j >> 1) * 8;
                int e = n0 + wn * 32 + nt * 8 + 2 * t + (j & 1);
                int ecol = e & 255;
                int h = ecol >> 5, d = ecol & 31;
                int b = row >> 11, s = row & 2047;
                float val = c[mt][nt][j] + bsel[ecol];
                if (msel == 2) {
                    g_v[(((size_t)(b * HH + h) * SSZ + s) * 32) + d] = val;
                } else {
                    __nv_bfloat16 hi = __float2bfloat16(val);
                    __nv_bfloat16 lo = __float2bfloat16(val - __bfloat162float(hi));
                    size_t rb = ((size_t)(b * HH + h) * SSZ + s) * 96;
                    if (msel == 0) {
                        g_qA[rb + d] = hi;
                        g_qA[rb + 32 + d] = lo;
                        g_qA[rb + 64 + d] = hi;
                    } else {
                        g_kB[rb + d] = hi;
                        g_kB[rb + 32 + d] = hi;
                        g_kB[rb + 64 + d] = lo;
                    }
                }
            }
}

// ---------------------------------------------------------------------------
// Kernel 2: sliding-window V sums, 8 outputs per thread (running sum)
// ---------------------------------------------------------------------------
__global__ void vsum_kernel()
{
    int idx = blockIdx.x * blockDim.x + threadIdx.x;
    const int KB8 = KKEY / 8;                  // 252
    const int total = NBH * 32 * KB8;
    if (idx >= total) return;
    int d  = idx & 31;
    int kb = (idx >> 5) % KB8;
    int bh = idx / (32 * KB8);
    int k0 = kb * 8;
    const float* vp = &g_v[((size_t)bh * SSZ + k0) * 32 + d];
    float s = 0.f;
#pragma unroll
    for (int w = 0; w < WWIN; w++) s += vp[w * 32];
    __nv_bfloat16 h8[8], l8[8];
#pragma unroll
    for (int i = 0; i < 8; i++) {
        __nv_bfloat16 hi = __float2bfloat16(s);
        h8[i] = hi;
        l8[i] = __float2bfloat16(s - __bfloat162float(hi));
        if (i < 7) s += vp[(WWIN + i) * 32] - vp[i * 32];
    }
    size_t o = ((size_t)bh * 32 + d) * KKEY + k0;
    *(uint4*)&g_vsH[o] = *(uint4*)h8;
    *(uint4*)&g_vsL[o] = *(uint4*)l8;
}

// ---------------------------------------------------------------------------
// work-queue counter init
// ---------------------------------------------------------------------------
__global__ void ctr_init_kernel() { g_ctr = 148; }

// ---------------------------------------------------------------------------
// G phase: 8 warps (4m x 2n of 32x64), two 32-col halves
// ---------------------------------------------------------------------------
__device__ __forceinline__ void compute_G(char* sm, uint32_t sb, uint32_t kbuf_off,
                                          int w, int lane)
{
    float* G = (float*)(sm + OFF_G);
    int g = lane >> 2, t = lane & 3;
    int mw = w >> 1, nw = w & 1;
    int r0 = mw * 32, kb = nw * 64;
    uint32_t aG0 = sb + OFF_QA + (uint32_t)(r0 + (lane & 15)) * 208
                 + (lane >> 4) * 16;
    uint32_t aG1 = aG0 + 16 * 208;
    uint32_t bRow4 = ((uint32_t)(lane >> 4) * 8 + (lane & 7)) * 208
                   + ((lane >> 3) & 1) * 16;
    uint32_t kbase = sb + kbuf_off;

#pragma unroll
    for (int half = 0; half < 2; half++) {
        float c[2][4][4];
#pragma unroll
        for (int mi = 0; mi < 2; mi++)
#pragma unroll
            for (int ni = 0; ni < 4; ni++)
#pragma unroll
                for (int j = 0; j < 4; j++) c[mi][ni][j] = 0.f;
#pragma unroll
        for (int ks = 0; ks < 6; ks++) {
            uint32_t a0, a1, a2, a3, a4, a5, a6, a7;
            ldsm_x4(aG0 + ks * 32, a0, a1, a2, a3);
            ldsm_x4(aG1 + ks * 32, a4, a5, a6, a7);
#pragma unroll
            for (int p2 = 0; p2 < 2; p2++) {
                int colb = kb + half * 32 + p2 * 16;
                uint32_t b0, b1, b2, b3;
                ldsm_x4(kbase + (uint32_t)colb * 208 + bRow4 + ks * 32,
                        b0, b1, b2, b3);
                mma16816(c[0][2 * p2],     a0, a1, a2, a3, b0, b1);
                mma16816(c[1][2 * p2],     a4, a5, a6, a7, b0, b1);
                mma16816(c[0][2 * p2 + 1], a0, a1, a2, a3, b2, b3);
                mma16816(c[1][2 * p2 + 1], a4, a5, a6, a7, b2, b3);
            }
        }
#pragma unroll
        for (int mi = 0; mi < 2; mi++)
#pragma unroll
            for (int ni = 0; ni < 4; ni++) {
                int r = r0 + mi * 16 + g;
                int col = kb + half * 32 + ni * 8 + 2 * t;
                G[r * GLD + col]           = c[mi][ni][0];
                G[r * GLD + col + 1]       = c[mi][ni][1];
                G[(r + 8) * GLD + col]     = c[mi][ni][2];
                G[(r + 8) * GLD + col + 1] = c[mi][ni][3];
            }
    }
}

// ---------------------------------------------------------------------------
// Kernel 3: persistent HMMA attention with G/PV overlap + work stealing
// (round-13 structure, verified 697us config)
// ---------------------------------------------------------------------------
__global__ __launch_bounds__(NTH, 1) void attn_kernel(float* __restrict__ out)
{
    extern __shared__ char sm[];
    uint32_t sb = smem_u32(sm);
    uint16_t* tqq  = (uint16_t*)(sm + OFF_TQQ);
    uint16_t* tkk  = (uint16_t*)(sm + OFF_TKK);
    uint16_t* tlen = (uint16_t*)(sm + OFF_TLEN);
    float* den_s = (float*)(sm + OFF_DEN);
    int* next_s = (int*)(sm + OFF_NEXT);
    float* G = (float*)(sm + OFF_G);
    __nv_bfloat16* PH = (__nv_bfloat16*)(sm + OFF_PH);
    __nv_bfloat16* PL = (__nv_bfloat16*)(sm + OFF_PL);

    int tid = threadIdx.x;
    int w = tid >> 5, lane = tid & 31;
    int g = lane >> 2, t = lane & 3;

    if (tid == 0) {
        int c = 0;
        for (int t0 = 0; t0 < TQ; t0 += 32) {
            for (int d = -95; d <= 95; d++) {
                int ad = d < 0 ? -d : d;
                int L = 96 - ad;
                if (t0 >= L) continue;
                int qs0 = d > 0 ? d : 0, ks0 = d > 0 ? 0 : -d;
                tqq[c] = (uint16_t)(qs0 + t0);
                tkk[c] = (uint16_t)(ks0 + t0);
                int l = L - t0; tlen[c] = (uint16_t)(l < 32 ? l : 32);
                c++;
            }
        }
    }
    // const V rows 32..39 for BOTH buffers; VH row32 = ones (denominator)
    for (int idx = tid; idx < 416; idx += NTH) {
        int buf = idx / 208, rem = idx % 208;
        int tt = rem / 104, r2 = rem % 104;
        int r = 32 + r2 / 13, cb = r2 % 13;
        uint4 v = make_uint4(0, 0, 0, 0);
        if (tt == 0 && r == 32)
            v = make_uint4(0x3F803F80u, 0x3F803F80u, 0x3F803F80u, 0x3F803F80u);
        int off = tt ? (buf ? OFF_VL1 : OFF_VL0) : (buf ? OFF_VH1 : OFF_VH0);
        *(uint4*)(sm + off + r * 208 + cb * 16) = v;
    }

    // PV addressing constants
    uint32_t bRow4 = ((uint32_t)(lane >> 4) * 8 + (lane & 7)) * 208
                   + ((lane >> 3) & 1) * 16;
    uint32_t bRow2 = (uint32_t)(lane & 7) * 208 + ((lane >> 3) & 1) * 16;
    uint32_t aPHf = sb + OFF_PH + (uint32_t)((w - 8) * 16 + (lane & 15)) * 208
                  + (lane >> 4) * 16;
    uint32_t aPLf = aPHf + (OFF_PL - OFF_PH);

    float acc[4][4];
    int tile = blockIdx.x;

    for (;;) {
        int qt = tile % NQT, bh = tile / NQT;
        int q0 = qt * TQ;
        const uint4* qsrc = (const uint4*)(g_qA + (size_t)bh * SSZ * 96);
        const uint4* ksrc = (const uint4*)(g_kB + (size_t)bh * SSZ * 96);

        // per-tile prologue: Q halo, KB(0)->kb0, KB(1)->kb1, V(0)->v0
        for (int idx = tid; idx < 128 * 12; idx += NTH) {
            int r = idx / 12, cb = idx % 12;
            int gq = q0 - 16 + r;
            if (gq >= 0 && gq < SSZ)
                CP_ASYNC16(sb + OFF_QA + r * 208 + cb * 16,
                           (const void*)(qsrc + (size_t)gq * 12 + cb));
            else
                *(uint4*)(sm + OFF_QA + r * 208 + cb * 16) = make_uint4(0, 0, 0, 0);
        }
        for (int idx = tid; idx < 1536; idx += NTH) {
            int r = idx / 12, cb = idx % 12;
            CP_ASYNC16(sb + OFF_KB0 + r * 208 + cb * 16,
                       (const void*)(ksrc + (size_t)r * 12 + cb));
            CP_ASYNC16(sb + OFF_KB1 + r * 208 + cb * 16,
                       (const void*)(ksrc + (size_t)(TQ + r) * 12 + cb));
        }
        for (int idx = tid; idx < 768; idx += NTH) {
            int tt = idx / 384, rem = idx % 384;
            int d = rem / 12, cb = rem % 12;
            const __nv_bfloat16* src = (tt ? g_vsL : g_vsH)
                + ((size_t)bh * 32 + d) * KKEY + cb * 8;
            CP_ASYNC16(sb + (tt ? OFF_VL0 : OFF_VH0) + d * 208 + cb * 16,
                       (const void*)src);
        }
        CP_COMMIT();
        CP_WAIT0();
        __syncthreads();

        if (w < 8) compute_G(sm, sb, OFF_KB0, w, lane);

#pragma unroll
        for (int i = 0; i < 4; i++)
#pragma unroll
            for (int j = 0; j < 4; j++) acc[i][j] = 0.f;

        for (int kt = 0; kt < NKT; kt++) {
            __syncthreads();   // (A) G(kt) visible; PV(kt-1) done with P/V

            // --- phase C(kt); warps 12-15 prefetch ---
            if (tid < NCHUNK) {
                int qq = tqq[tid], kk = tkk[tid], len = tlen[tid];
                float s = 0.f;
#pragma unroll
                for (int ww = 0; ww < WWIN; ww++)
                    s += G[(qq + ww) * GLD + kk + ww];
                {
                    float p = __expf(s * SCALE);
                    __nv_bfloat16 hi = __float2bfloat16(p);
                    __nv_bfloat16 lo = __float2bfloat16(p - __bfloat162float(hi));
                    int off = qq * QLD + kk;
                    PH[off] = hi;
                    PL[off] = lo;
                }
#pragma unroll 4
                for (int u = 1; u < 32; u++) {
                    int uu = (u < len) ? u : (len - 1);
                    s += G[(qq + uu + 32) * GLD + (kk + uu + 32)]
                       - G[(qq + uu - 1) * GLD + (kk + uu - 1)];
                    if (u < len) {
                        float p = __expf(s * SCALE);
                        __nv_bfloat16 hi = __float2bfloat16(p);
                        __nv_bfloat16 lo = __float2bfloat16(p - __bfloat162float(hi));
                        int off = (qq + u) * QLD + (kk + u);
                        PH[off] = hi;
                        PL[off] = lo;
                    }
                }
            } else if (tid >= 384) {
                int pt = tid - 384;
                if (kt + 2 < NKT) {
                    int k0n = (kt + 2) * TQ;
                    uint32_t kdst = sb + ((kt & 1) ? OFF_KB1 : OFF_KB0);
                    for (int idx = pt; idx < 1536; idx += 128) {
                        int r = idx / 12, cb = idx % 12;
                        CP_ASYNC16(kdst + r * 208 + cb * 16,
                                   (const void*)(ksrc + (size_t)(k0n + r) * 12 + cb));
                    }
                }
                if (kt + 1 < NKT) {
                    int k0n = (kt + 1) * TQ;
                    for (int idx = pt; idx < 768; idx += 128) {
                        int tt = idx / 384, rem = idx % 384;
                        int d = rem / 12, cb = rem % 12;
                        const __nv_bfloat16* src = (tt ? g_vsL : g_vsH)
                            + ((size_t)bh * 32 + d) * KKEY + k0n + cb * 8;
                        int off = tt ? (((kt + 1) & 1) ? OFF_VL1 : OFF_VL0)
                                     : (((kt + 1) & 1) ? OFF_VH1 : OFF_VH0);
                        CP_ASYNC16(sb + off + d * 208 + cb * 16, (const void*)src);
                    }
                }
            }
            CP_COMMIT();
            CP_WAIT1();
            __syncthreads();   // (B) P visible; KB(kt+1)/V(kt) arrived

            // --- overlap: G(kt+1) on warps 0-7, PV(kt) on warps 8-15 ---
            if (w < 8) {
                if (kt + 1 < NKT)
                    compute_G(sm, sb, ((kt + 1) & 1) ? OFF_KB1 : OFF_KB0, w, lane);
            } else {
                uint32_t vhb = sb + ((kt & 1) ? OFF_VH1 : OFF_VH0);
                uint32_t vlb = sb + ((kt & 1) ? OFF_VL1 : OFF_VL0);
                if (w < 14) {
#pragma unroll
                    for (int pass = 0; pass < 3; pass++) {
                        uint32_t Ab = (pass == 1) ? aPLf : aPHf;
                        uint32_t Bb = (pass == 2) ? vlb : vhb;
#pragma unroll
                        for (int ks = 0; ks < 6; ks++) {
                            uint32_t a0, a1, a2, a3;
                            ldsm_x4(Ab + ks * 32, a0, a1, a2, a3);
                            uint32_t b0, b1, b2, b3;
                            ldsm_x4(Bb + bRow4 + ks * 32, b0, b1, b2, b3);
                            mma16816(acc[0], a0, a1, a2, a3, b0, b1);
                            mma16816(acc[1], a0, a1, a2, a3, b2, b3);
                            ldsm_x4(Bb + 16 * 208 + bRow4 + ks * 32, b0, b1, b2, b3);
                            mma16816(acc[2], a0, a1, a2, a3, b0, b1);
                            mma16816(acc[3], a0, a1, a2, a3, b2, b3);
                        }
                    }
                } else {
                    int base = (w - 14) * 3;
#pragma unroll
                    for (int st = 0; st < 3; st++) {
                        uint32_t aPh = sb + OFF_PH
                            + (uint32_t)((base + st) * 16 + (lane & 15)) * 208
                            + (lane >> 4) * 16;
                        uint32_t aPl = aPh + (OFF_PL - OFF_PH);
#pragma unroll
                        for (int pass = 0; pass < 3; pass++) {
                            uint32_t Ab = (pass == 1) ? aPl : aPh;
                            uint32_t Bb = (pass == 2) ? vlb : vhb;
#pragma unroll
                            for (int ks = 0; ks < 6; ks++) {
                                uint32_t a0, a1, a2, a3;
                                ldsm_x4(Ab + ks * 32, a0, a1, a2, a3);
                                uint32_t b0, b1;
                                ldsm_x2(Bb + 32 * 208 + bRow2 + ks * 32, b0, b1);
                                mma16816(acc[st], a0, a1, a2, a3, b0, b1);
                            }
                        }
                    }
                }
            }
        }

        // denominator from warps 14/15 (col 32 -> t==0, j 0/2)
        if (w >= 14 && t == 0) {
            int base = (w - 14) * 3;
#pragma unroll
            for (int st = 0; st < 3; st++) {
                den_s[(base + st) * 16 + g]     = acc[st][0];
                den_s[(base + st) * 16 + g + 8] = acc[st][2];
            }
        }
        __syncthreads();

        if (w >= 8 && w < 14) {
            int stripe = w - 8;
            int b = bh >> 3, h = bh & 7;
#pragma unroll
            for (int mi = 0; mi < 2; mi++) {
                int rr = stripe * 16 + g + mi * 8;
                int q = q0 + rr;
                if (q < SSZ) {
                    float dinv = 1.f / den_s[rr];
                    float* orow = out + ((size_t)b * SSZ + q) * EE + h * 32;
#pragma unroll
                    for (int nt = 0; nt < 4; nt++) {
                        int col = nt * 8 + 2 * t;
                        orow[col]     = acc[nt][mi * 2]     * dinv;
                        orow[col + 1] = acc[nt][mi * 2 + 1] * dinv;
                    }
                }
            }
        }
        if (tid == 0) next_s[0] = atomicAdd(&g_ctr, 1);
        __syncthreads();   // next tile visible; everyone done with QA/P/V/den
        tile = next_s[0];
        if (tile >= NTILES) break;
    }
}

// ---------------------------------------------------------------------------
extern "C" void kernel_launch(void* const* d_in, const int* in_sizes, int n_in,
                              void* d_out, int out_size)
{
    const float* x  = (const float*)d_in[0];
    const float* Wq = (const float*)d_in[1];
    const float* bq = (const float*)d_in[2];
    const float* Wk = (const float*)d_in[3];
    const float* bk = (const float*)d_in[4];
    const float* Wv = (const float*)d_in[5];
    const float* bv = (const float*)d_in[6];
    float* out = (float*)d_out;

    xsplit_kernel<<<(8192 * 64 + 255) / 256, 256>>>(x);
    wsplit_kernel<<<(768 * 256 + 255) / 256, 256>>>(Wq, Wk, Wv);
    ctr_init_kernel<<<1, 1>>>();
    {
        cudaFuncSetAttribute(proj_mma_kernel,
                             cudaFuncAttributeMaxDynamicSharedMemorySize,
                             PJ_SMEM);
        dim3 grid(12, 64);
        proj_mma_kernel<<<grid, 256, PJ_SMEM>>>(bq, bk, bv);
    }
    {
        const int total = NBH * 32 * (KKEY / 8);
        vsum_kernel<<<(total + 255) / 256, 256>>>();
    }
    {
        cudaFuncSetAttribute(attn_kernel,
                             cudaFuncAttributeMaxDynamicSharedMemorySize,
                             SMEM_TOTAL);
        attn_kernel<<<148, NTH, SMEM_TOTAL>>>(out);
    }
}